// round 10
// baseline (speedup 1.0000x reference)
#include <cuda_runtime.h>
#include <cuda_fp16.h>
#include <stdint.h>

#define F    128
#define H1   64
#define H2   32
#define NC   10
#define NPB  7          // nodes per block
#define RV   119        // valid rows = 7*17
#define THREADS 256     // 8 warps: 4(M) x 2(N)

// ---- dynamic shared layout ----
#define SM_AHI  0            // 128x128 fp16 (32KB), swizzled
#define SM_HB   0            // Hbuf 128x65 f32 (33280) overlays AHI after GEMM
#define SM_RBUF 33280        // 7 * 68 floats (padded) = 1904
#define SM_YBUF 35200        // 7 * 36 floats (padded) = 1008
#define SM_WCQ  36224        // 80 float4 = 1280
#define SM_TOTAL 37632       // -> 4 CTAs/SM (smem & 64-reg cap)

// precomputed W1 MMA fragments + blocked W2
__device__ uint4  gBhi[8 * 4 * 32];     // [kc][ntile tp][lane]
__device__ float4 gW2blk[16 * 8 * 4];   // [jq][mq][i] : .k = W2[mq*4+k][jq*4+i]

// fp16 tile: row stride 256B, 16 chunks of 16B; swizzle chunk ^= (row&7)
static __device__ __forceinline__ uint32_t sw_off(int row, int chunk) {
    return (uint32_t)row * 256u + (uint32_t)((chunk ^ (row & 7)) << 4);
}
static __device__ __forceinline__ uint32_t smem_u32(const void* p) {
    uint32_t a;
    asm("{ .reg .u64 t; cvta.to.shared.u64 t, %1; cvt.u32.u64 %0, t; }" : "=r"(a) : "l"(p));
    return a;
}
static __device__ __forceinline__ void ldsm_x4(uint32_t* r, uint32_t addr) {
    asm volatile("ldmatrix.sync.aligned.m8n8.x4.shared.b16 {%0,%1,%2,%3}, [%4];"
                 : "=r"(r[0]), "=r"(r[1]), "=r"(r[2]), "=r"(r[3]) : "r"(addr));
}
static __device__ __forceinline__ void mma16816(float* c, const uint32_t* a,
                                                uint32_t b0, uint32_t b1) {
    asm volatile(
        "mma.sync.aligned.m16n8k16.row.col.f32.f16.f16.f32 "
        "{%0,%1,%2,%3}, {%4,%5,%6,%7}, {%8,%9}, {%0,%1,%2,%3};"
        : "+f"(c[0]), "+f"(c[1]), "+f"(c[2]), "+f"(c[3])
        : "r"(a[0]), "r"(a[1]), "r"(a[2]), "r"(a[3]), "r"(b0), "r"(b1));
}
static __device__ __forceinline__ uint2 pack4(__half h0, __half h1, __half h2, __half h3) {
    __half2 a = __halves2half2(h0, h1);
    __half2 b = __halves2half2(h2, h3);
    uint2 r;
    r.x = *(const uint32_t*)&a;
    r.y = *(const uint32_t*)&b;
    return r;
}

// ---- init kernel: W1 fp16 fragments (replaying the ldsm path) + blocked W2 ----
__global__ void gcn_init_kernel(const float* __restrict__ W1,
                                const float* __restrict__ W2)
{
    __shared__ __align__(16) char bsm[16384];    // BHI
    const int tid = threadIdx.x, wid = tid >> 5, lane = tid & 31;

    const float4* W1v = (const float4*)W1;
    #pragma unroll
    for (int t = 0; t < 8; t++) {
        int gi = tid + t * 256;          // gi = j*32 + f4
        int j = gi >> 5, f4 = gi & 31;
        float4 v = W1v[gi];
        __half h0 = __float2half_rn(v.x), h1 = __float2half_rn(v.y);
        __half h2 = __float2half_rn(v.z), h3 = __float2half_rn(v.w);
        uint32_t off = sw_off(j, f4 >> 1) + (uint32_t)(f4 & 1) * 8u;
        *(uint2*)(bsm + off) = pack4(h0, h1, h2, h3);
    }
    // blocked W2: gW2blk[jq*32 + mq*4 + i].k = W2[(mq*4+k)][jq*4+i]
    #pragma unroll
    for (int t = 0; t < 2; t++) {
        int idx = tid + t * 256;         // 0..511
        int jq = idx >> 5, mq = (idx >> 2) & 7, i = idx & 3;
        int j = jq * 4 + i, m0 = mq * 4;
        gW2blk[idx] = make_float4(W2[(m0 + 0) * H1 + j], W2[(m0 + 1) * H1 + j],
                                  W2[(m0 + 2) * H1 + j], W2[(m0 + 3) * H1 + j]);
    }
    __syncthreads();

    const uint32_t sb = smem_u32(bsm);
    const int kc = wid;                  // warp w -> k-chunk w
    #pragma unroll
    for (int tp = 0; tp < 4; tp++) {
        int row = 16 * tp + ((lane >> 4) << 3) + (lane & 7);
        int chunk = kc * 2 + ((lane >> 3) & 1);
        uint32_t rh[4];
        ldsm_x4(rh, sb + sw_off(row, chunk));
        gBhi[(kc * 4 + tp) * 32 + lane] = make_uint4(rh[0], rh[1], rh[2], rh[3]);
    }
}

__global__ __launch_bounds__(THREADS, 4) void gcn_mma_kernel(
    const float* __restrict__ x,  const float* __restrict__ nb,
    const float* __restrict__ Wc, float* __restrict__ out, int n)
{
    extern __shared__ char sm[];
    const uint32_t sb = smem_u32(sm);
    const int tid = threadIdx.x, wid = tid >> 5, lane = tid & 31;
    const long gbase = (long)blockIdx.x * NPB;

    // ---- WCQ[mq*10+c] = float4 of Wc[c][mq*4 .. +3] ----
    if (tid < 80) {
        int mq = tid / 10, c = tid - mq * 10;
        const float* w = Wc + c * H2 + mq * 4;
        ((float4*)(sm + SM_WCQ))[tid] = make_float4(w[0], w[1], w[2], w[3]);
    }

    // ---- A rows: warp w owns rows w + 8t (t<15), 3 batches of 5 (MLP=5) ----
    #pragma unroll 1
    for (int b0 = 0; b0 < 15; b0 += 5) {
        float4 q[5];
        #pragma unroll
        for (int t = 0; t < 5; t++) {
            int r = wid + (b0 + t) * 8;
            q[t] = make_float4(0.f, 0.f, 0.f, 0.f);
            if (r < RV) {
                int node = r / 17, sub = r - node * 17;
                long gnode = gbase + node;
                if (gnode < n) {
                    const float4* src = (sub == 0)
                        ? (const float4*)(x + gnode * (long)F)
                        : (const float4*)(nb + (gnode * 16 + (sub - 1)) * (long)F);
                    q[t] = src[lane];
                }
            }
        }
        #pragma unroll
        for (int t = 0; t < 5; t++) {
            int r = wid + (b0 + t) * 8;
            if (r < RV) {
                float4 v = q[t];
                float ss = v.x * v.x + v.y * v.y + v.z * v.z + v.w * v.w;
                #pragma unroll
                for (int o = 16; o > 0; o >>= 1) ss += __shfl_xor_sync(0xffffffffu, ss, o);
                float inv = 1.f / fmaxf(sqrtf(ss), 1e-12f);
                __half h0 = __float2half_rn(v.x * inv);
                __half h1 = __float2half_rn(v.y * inv);
                __half h2 = __float2half_rn(v.z * inv);
                __half h3 = __float2half_rn(v.w * inv);
                uint32_t off = sw_off(r, lane >> 1) + (uint32_t)(lane & 1) * 8u;
                *(uint2*)(sm + SM_AHI + off) = pack4(h0, h1, h2, h3);
            }
        }
    }

    // ---- zero padding rows 119..127 ----
    if (tid < 144) {
        int r = RV + tid / 16, ch = tid & 15;
        *(uint4*)(sm + SM_AHI + sw_off(r, ch)) = make_uint4(0, 0, 0, 0);
    }
    __syncthreads();

    // ---- GEMM: warp grid 4(M) x 2(N); warp tile M=32 x N=32 ----
    const int wm = wid >> 1, wn = wid & 1;
    float acc[2][4][4];
    #pragma unroll
    for (int m = 0; m < 2; m++)
        #pragma unroll
        for (int ntl = 0; ntl < 4; ntl++)
            acc[m][ntl][0] = acc[m][ntl][1] = acc[m][ntl][2] = acc[m][ntl][3] = 0.f;

    {
        const int arow = 32 * wm + (lane & 15);
        const int asel = lane >> 4;
        const int tpb = 2 * wn;
        const uint4* pBhi = gBhi + tpb * 32 + lane;

        #pragma unroll
        for (int kc = 0; kc < 8; kc++) {
            uint4 bh0 = pBhi[kc * 128];
            uint4 bh1 = pBhi[kc * 128 + 32];

            uint32_t ahi[2][4];
            #pragma unroll
            for (int m = 0; m < 2; m++)
                ldsm_x4(ahi[m], sb + SM_AHI + sw_off(arow + 16 * m, kc * 2 + asel));

            #pragma unroll
            for (int m = 0; m < 2; m++) {
                mma16816(acc[m][0], ahi[m], bh0.x, bh0.y);
                mma16816(acc[m][1], ahi[m], bh0.z, bh0.w);
                mma16816(acc[m][2], ahi[m], bh1.x, bh1.y);
                mma16816(acc[m][3], ahi[m], bh1.z, bh1.w);
            }
        }
    }
    __syncthreads();   // A tile dead; Hbuf overlays it

    // ---- write C frags to Hbuf[128][65] ----
    float* hb = (float*)(sm + SM_HB);
    #pragma unroll
    for (int m = 0; m < 2; m++) {
        int r0 = 32 * wm + 16 * m + (lane >> 2);
        int c0 = 32 * wn + (lane & 3) * 2;
        #pragma unroll
        for (int ntl = 0; ntl < 4; ntl++) {
            int c = c0 + ntl * 8;
            hb[r0 * 65 + c]           = acc[m][ntl][0];
            hb[r0 * 65 + c + 1]       = acc[m][ntl][1];
            hb[(r0 + 8) * 65 + c]     = acc[m][ntl][2];
            hb[(r0 + 8) * 65 + c + 1] = acc[m][ntl][3];
        }
    }
    __syncthreads();

    // ---- stage 1: per-node r-reduction -> rbuf (padded stride 68) ----
    if (wid < NPB) {
        int base = wid * 17;
        float hx0 = hb[base * 65 + lane], hx1 = hb[base * 65 + 32 + lane];
        float r0 = 0.f, r1 = 0.f;
        #pragma unroll
        for (int k = 0; k < 16; k++) {
            const float* hr = hb + (base + 1 + k) * 65;
            r0 += fmaxf(hx0 + hr[lane], 0.f);
            r1 += fmaxf(hx1 + hr[32 + lane], 0.f);
        }
        float* rb = (float*)(sm + SM_RBUF) + wid * 68;
        rb[lane]      = r0;
        rb[lane + 32] = r1;
    }
    __syncthreads();

    // ---- stage 2: y = relu(r @ W2^T), 2 warps, register-blocked 4x4 ----
    if (wid < 2) {
        int nn = wid * 4 + (lane >> 3);      // node
        int mq = lane & 7;                    // m-quad
        if (nn < NPB) {
            const float4* rb4 = (const float4*)((float*)(sm + SM_RBUF) + nn * 68);
            const float4* wblk = gW2blk + mq * 4;
            float y0 = 0.f, y1 = 0.f, y2 = 0.f, y3 = 0.f;
            #pragma unroll
            for (int jq = 0; jq < 16; jq++) {
                float4 r4 = rb4[jq];
                float4 w0 = wblk[jq * 32 + 0];
                float4 w1 = wblk[jq * 32 + 1];
                float4 w2 = wblk[jq * 32 + 2];
                float4 w3 = wblk[jq * 32 + 3];
                y0 += r4.x * w0.x + r4.y * w1.x + r4.z * w2.x + r4.w * w3.x;
                y1 += r4.x * w0.y + r4.y * w1.y + r4.z * w2.y + r4.w * w3.y;
                y2 += r4.x * w0.z + r4.y * w1.z + r4.z * w2.z + r4.w * w3.z;
                y3 += r4.x * w0.w + r4.y * w1.w + r4.z * w2.w + r4.w * w3.w;
            }
            float4* yb = (float4*)((float*)(sm + SM_YBUF) + nn * 36 + mq * 4);
            *yb = make_float4(fmaxf(y0, 0.f), fmaxf(y1, 0.f),
                              fmaxf(y2, 0.f), fmaxf(y3, 0.f));
        }
    }
    __syncthreads();

    // ---- stage 3: out = y @ Wc^T, per-node warps, float4 blocked ----
    long gnode = gbase + wid;
    if (wid < NPB && gnode < n && lane < NC) {
        const float4* yb4 = (const float4*)((float*)(sm + SM_YBUF) + wid * 36);
        const float4* wcq = (const float4*)(sm + SM_WCQ);
        float o = 0.f;
        #pragma unroll
        for (int mq = 0; mq < 8; mq++) {
            float4 y4 = yb4[mq];
            float4 w4 = wcq[mq * 10 + lane];
            o += y4.x * w4.x + y4.y * w4.y + y4.z * w4.z + y4.w * w4.w;
        }
        out[gnode * NC + lane] = o;
    }
}

extern "C" void kernel_launch(void* const* d_in, const int* in_sizes, int n_in,
                              void* d_out, int out_size)
{
    const float* x  = (const float*)d_in[0];
    const float* nb = (const float*)d_in[1];
    const float* W1 = (const float*)d_in[2];
    const float* W2 = (const float*)d_in[3];
    const float* Wc = (const float*)d_in[4];
    float* out = (float*)d_out;

    int n = in_sizes[0] / F;
    gcn_init_kernel<<<1, 256>>>(W1, W2);
    cudaFuncSetAttribute(gcn_mma_kernel,
                         cudaFuncAttributeMaxDynamicSharedMemorySize, SM_TOTAL);
    int grid = (n + NPB - 1) / NPB;
    gcn_mma_kernel<<<grid, THREADS, SM_TOTAL>>>(x, nb, Wc, out, n);
}

// round 11
// speedup vs baseline: 1.1543x; 1.1543x over previous
#include <cuda_runtime.h>
#include <cuda_fp16.h>
#include <stdint.h>

#define F    128
#define H1   64
#define H2   32
#define NC   10
#define NPB  7          // nodes per block
#define RV   119        // valid rows = 7*17
#define THREADS 256     // 8 warps: 4(M) x 2(N)

// ---- dynamic shared layout ----
#define SM_AHI  0            // 128x128 fp16 (32KB), swizzled
#define SM_HB   0            // Hbuf 128x65 f32 (33280) overlays AHI after GEMM
#define SM_RBUF 33280        // 7*64*4 = 1792 (16B aligned)
#define SM_YBUF 35072        // 7*32*4 = 896
#define SM_WCQ  35968        // 80 float4 = 1280
#define SM_TOTAL 37248       // -> 4 CTAs/SM (smem & 64-reg cap)

// precomputed W1 MMA fragments + packed W2
__device__ uint4   gBhi[8 * 4 * 32];   // [kc][ntile tp][lane]
__device__ __half2 gW2h[32 * 32];      // [jp][m] = (W2[m][2jp], W2[m][2jp+1])

// fp16 tile: row stride 256B, 16 chunks of 16B; swizzle chunk ^= (row&7)
static __device__ __forceinline__ uint32_t sw_off(int row, int chunk) {
    return (uint32_t)row * 256u + (uint32_t)((chunk ^ (row & 7)) << 4);
}
static __device__ __forceinline__ uint32_t smem_u32(const void* p) {
    uint32_t a;
    asm("{ .reg .u64 t; cvta.to.shared.u64 t, %1; cvt.u32.u64 %0, t; }" : "=r"(a) : "l"(p));
    return a;
}
static __device__ __forceinline__ void ldsm_x4(uint32_t* r, uint32_t addr) {
    asm volatile("ldmatrix.sync.aligned.m8n8.x4.shared.b16 {%0,%1,%2,%3}, [%4];"
                 : "=r"(r[0]), "=r"(r[1]), "=r"(r[2]), "=r"(r[3]) : "r"(addr));
}
static __device__ __forceinline__ void mma16816(float* c, const uint32_t* a,
                                                uint32_t b0, uint32_t b1) {
    asm volatile(
        "mma.sync.aligned.m16n8k16.row.col.f32.f16.f16.f32 "
        "{%0,%1,%2,%3}, {%4,%5,%6,%7}, {%8,%9}, {%0,%1,%2,%3};"
        : "+f"(c[0]), "+f"(c[1]), "+f"(c[2]), "+f"(c[3])
        : "r"(a[0]), "r"(a[1]), "r"(a[2]), "r"(a[3]), "r"(b0), "r"(b1));
}
static __device__ __forceinline__ uint2 pack4(__half h0, __half h1, __half h2, __half h3) {
    __half2 a = __halves2half2(h0, h1);
    __half2 b = __halves2half2(h2, h3);
    uint2 r;
    r.x = *(const uint32_t*)&a;
    r.y = *(const uint32_t*)&b;
    return r;
}

// ---- init kernel: W1 fp16 fragments (replaying the ldsm path) + packed W2 ----
__global__ void gcn_init_kernel(const float* __restrict__ W1,
                                const float* __restrict__ W2)
{
    __shared__ __align__(16) char bsm[16384];    // BHI
    const int tid = threadIdx.x, wid = tid >> 5, lane = tid & 31;

    const float4* W1v = (const float4*)W1;
    #pragma unroll
    for (int t = 0; t < 8; t++) {
        int gi = tid + t * 256;          // gi = j*32 + f4
        int j = gi >> 5, f4 = gi & 31;
        float4 v = W1v[gi];
        __half h0 = __float2half_rn(v.x), h1 = __float2half_rn(v.y);
        __half h2 = __float2half_rn(v.z), h3 = __float2half_rn(v.w);
        uint32_t off = sw_off(j, f4 >> 1) + (uint32_t)(f4 & 1) * 8u;
        *(uint2*)(bsm + off) = pack4(h0, h1, h2, h3);
    }
    // gW2h[jp*32+m] = (W2[m][2jp], W2[m][2jp+1])  (W2 global: [m][j], m<32, j<64)
    for (int idx = tid; idx < 32 * 32; idx += 256) {
        int jp = idx >> 5, m = idx & 31;
        gW2h[idx] = __halves2half2(__float2half_rn(W2[m * H1 + 2 * jp]),
                                   __float2half_rn(W2[m * H1 + 2 * jp + 1]));
    }
    __syncthreads();

    const uint32_t sb = smem_u32(bsm);
    const int kc = wid;                  // warp w -> k-chunk w
    #pragma unroll
    for (int tp = 0; tp < 4; tp++) {
        int row = 16 * tp + ((lane >> 4) << 3) + (lane & 7);
        int chunk = kc * 2 + ((lane >> 3) & 1);
        uint32_t rh[4];
        ldsm_x4(rh, sb + sw_off(row, chunk));
        gBhi[(kc * 4 + tp) * 32 + lane] = make_uint4(rh[0], rh[1], rh[2], rh[3]);
    }
}

__global__ __launch_bounds__(THREADS, 4) void gcn_mma_kernel(
    const float* __restrict__ x,  const float* __restrict__ nb,
    const float* __restrict__ Wc, float* __restrict__ out, int n)
{
    extern __shared__ char sm[];
    const uint32_t sb = smem_u32(sm);
    const int tid = threadIdx.x, wid = tid >> 5, lane = tid & 31;
    const long gbase = (long)blockIdx.x * NPB;

    // ---- WCQ[mq*10+c] = float4 of Wc[c][mq*4 .. +3] ----
    if (tid < 80) {
        int mq = tid / 10, c = tid - mq * 10;
        const float* w = Wc + c * H2 + mq * 4;
        ((float4*)(sm + SM_WCQ))[tid] = make_float4(w[0], w[1], w[2], w[3]);
    }

    // ---- A rows: warp w owns rows w + 8t (t<15), 3 batches of 5 (MLP=5) ----
    #pragma unroll 1
    for (int b0 = 0; b0 < 15; b0 += 5) {
        float4 q[5];
        #pragma unroll
        for (int t = 0; t < 5; t++) {
            int r = wid + (b0 + t) * 8;
            q[t] = make_float4(0.f, 0.f, 0.f, 0.f);
            if (r < RV) {
                int node = r / 17, sub = r - node * 17;
                long gnode = gbase + node;
                if (gnode < n) {
                    const float4* src = (sub == 0)
                        ? (const float4*)(x + gnode * (long)F)
                        : (const float4*)(nb + (gnode * 16 + (sub - 1)) * (long)F);
                    q[t] = src[lane];
                }
            }
        }
        #pragma unroll
        for (int t = 0; t < 5; t++) {
            int r = wid + (b0 + t) * 8;
            if (r < RV) {
                float4 v = q[t];
                float ss = v.x * v.x + v.y * v.y + v.z * v.z + v.w * v.w;
                #pragma unroll
                for (int o = 16; o > 0; o >>= 1) ss += __shfl_xor_sync(0xffffffffu, ss, o);
                float inv = 1.f / fmaxf(sqrtf(ss), 1e-12f);
                __half h0 = __float2half_rn(v.x * inv);
                __half h1 = __float2half_rn(v.y * inv);
                __half h2 = __float2half_rn(v.z * inv);
                __half h3 = __float2half_rn(v.w * inv);
                uint32_t off = sw_off(r, lane >> 1) + (uint32_t)(lane & 1) * 8u;
                *(uint2*)(sm + SM_AHI + off) = pack4(h0, h1, h2, h3);
            }
        }
    }

    // ---- zero padding rows 119..127 ----
    if (tid < 144) {
        int r = RV + tid / 16, ch = tid & 15;
        *(uint4*)(sm + SM_AHI + sw_off(r, ch)) = make_uint4(0, 0, 0, 0);
    }
    __syncthreads();

    // ---- GEMM: warp grid 4(M) x 2(N); warp tile M=32 x N=32 ----
    const int wm = wid >> 1, wn = wid & 1;
    float acc[2][4][4];
    #pragma unroll
    for (int m = 0; m < 2; m++)
        #pragma unroll
        for (int ntl = 0; ntl < 4; ntl++)
            acc[m][ntl][0] = acc[m][ntl][1] = acc[m][ntl][2] = acc[m][ntl][3] = 0.f;

    {
        const int arow = 32 * wm + (lane & 15);
        const int asel = lane >> 4;
        const int tpb = 2 * wn;
        const uint4* pBhi = gBhi + tpb * 32 + lane;

        #pragma unroll
        for (int kc = 0; kc < 8; kc++) {
            uint4 bh0 = pBhi[kc * 128];
            uint4 bh1 = pBhi[kc * 128 + 32];

            uint32_t ahi[2][4];
            #pragma unroll
            for (int m = 0; m < 2; m++)
                ldsm_x4(ahi[m], sb + SM_AHI + sw_off(arow + 16 * m, kc * 2 + asel));

            #pragma unroll
            for (int m = 0; m < 2; m++) {
                mma16816(acc[m][0], ahi[m], bh0.x, bh0.y);
                mma16816(acc[m][1], ahi[m], bh0.z, bh0.w);
                mma16816(acc[m][2], ahi[m], bh1.x, bh1.y);
                mma16816(acc[m][3], ahi[m], bh1.z, bh1.w);
            }
        }
    }
    __syncthreads();   // A tile dead; Hbuf overlays it

    // ---- write C frags to Hbuf[128][65] ----
    float* hb = (float*)(sm + SM_HB);
    #pragma unroll
    for (int m = 0; m < 2; m++) {
        int r0 = 32 * wm + 16 * m + (lane >> 2);
        int c0 = 32 * wn + (lane & 3) * 2;
        #pragma unroll
        for (int ntl = 0; ntl < 4; ntl++) {
            int c = c0 + ntl * 8;
            hb[r0 * 65 + c]           = acc[m][ntl][0];
            hb[r0 * 65 + c + 1]       = acc[m][ntl][1];
            hb[(r0 + 8) * 65 + c]     = acc[m][ntl][2];
            hb[(r0 + 8) * 65 + c + 1] = acc[m][ntl][3];
        }
    }
    __syncthreads();

    // ---- per-node epilogue: warp = node (7 warps) ----
    long gnode = gbase + wid;
    if (wid < NPB && gnode < n) {
        int base = wid * 17;
        // stage 1: r = sum_k relu(hx + hk)
        float hx0 = hb[base * 65 + lane], hx1 = hb[base * 65 + 32 + lane];
        float r0 = 0.f, r1 = 0.f;
        #pragma unroll
        for (int k = 0; k < 16; k++) {
            const float* hr = hb + (base + 1 + k) * 65;
            r0 += fmaxf(hx0 + hr[lane], 0.f);
            r1 += fmaxf(hx1 + hr[32 + lane], 0.f);
        }
        float* rb = (float*)(sm + SM_RBUF) + wid * 64;
        rb[lane]      = r0;
        rb[lane + 32] = r1;
        __syncwarp();

        // stage 2: y[lane] = relu(sum_j r[j] * W2[lane][j]), vectorized
        const float4* rb4 = (const float4*)rb;
        const __half2* w2 = gW2h + lane;
        float y = 0.f;
        #pragma unroll
        for (int jq = 0; jq < 16; jq++) {
            float4 r4 = rb4[jq];
            __half2 wa = w2[(2 * jq) * 32];
            __half2 wb = w2[(2 * jq + 1) * 32];
            y += r4.x * __low2float(wa) + r4.y * __high2float(wa)
               + r4.z * __low2float(wb) + r4.w * __high2float(wb);
        }
        y = fmaxf(y, 0.f);
        float* yb = (float*)(sm + SM_YBUF) + wid * 32;
        yb[lane] = y;
        __syncwarp();

        // stage 3: out[c] = sum_m y[m] * Wc[c][m], float4 blocked
        if (lane < NC) {
            const float4* yb4 = (const float4*)yb;
            const float4* wcq = (const float4*)(sm + SM_WCQ);
            float o = 0.f;
            #pragma unroll
            for (int mq = 0; mq < 8; mq++) {
                float4 y4 = yb4[mq];
                float4 w4 = wcq[mq * 10 + lane];
                o += y4.x * w4.x + y4.y * w4.y + y4.z * w4.z + y4.w * w4.w;
            }
            out[gnode * NC + lane] = o;
        }
    }
}

extern "C" void kernel_launch(void* const* d_in, const int* in_sizes, int n_in,
                              void* d_out, int out_size)
{
    const float* x  = (const float*)d_in[0];
    const float* nb = (const float*)d_in[1];
    const float* W1 = (const float*)d_in[2];
    const float* W2 = (const float*)d_in[3];
    const float* Wc = (const float*)d_in[4];
    float* out = (float*)d_out;

    int n = in_sizes[0] / F;
    gcn_init_kernel<<<1, 256>>>(W1, W2);
    cudaFuncSetAttribute(gcn_mma_kernel,
                         cudaFuncAttributeMaxDynamicSharedMemorySize, SM_TOTAL);
    int grid = (n + NPB - 1) / NPB;
    gcn_mma_kernel<<<grid, THREADS, SM_TOTAL>>>(x, nb, Wc, out, n);
}

// round 12
// speedup vs baseline: 1.3116x; 1.1362x over previous
#include <cuda_runtime.h>
#include <cuda_fp16.h>
#include <stdint.h>

#define F    128
#define H1   64
#define H2   32
#define NC   10
#define NPB  7          // nodes per block
#define RV   119        // valid rows = 7*17
#define THREADS 256     // 8 warps: 4(M) x 2(N)

// ---- dynamic shared layout ----
#define SM_AHI  0            // 128x128 fp16 (32KB), swizzled
#define SM_HB   0            // Hbuf 128x64 fp16 (16KB, swizzled) overlays AHI after GEMM
#define SM_RBUF 33280        // 7*64*4 = 1792 (16B aligned)
#define SM_YBUF 35072        // 7*32*4 = 896
#define SM_WCQ  35968        // 80 float4 = 1280
#define SM_TOTAL 37248       // -> 4 CTAs/SM (smem & 64-reg cap)

// precomputed W1 MMA fragments + packed W2
__device__ uint4   gBhi[8 * 4 * 32];   // [kc][ntile tp][lane]
__device__ __half2 gW2h[32 * 32];      // [jp][m] = (W2[m][2jp], W2[m][2jp+1])

// A-tile: row stride 256B, 16 chunks of 16B; swizzle chunk ^= (row&7)
static __device__ __forceinline__ uint32_t sw_off(int row, int chunk) {
    return (uint32_t)row * 256u + (uint32_t)((chunk ^ (row & 7)) << 4);
}
// fp16 Hbuf: row stride 128B, 8 chunks of 16B; swizzle chunk ^= (row&7)
static __device__ __forceinline__ uint32_t hb_off(int row, int chunk) {
    return (uint32_t)row * 128u + (uint32_t)((chunk ^ (row & 7)) << 4);
}
static __device__ __forceinline__ uint32_t smem_u32(const void* p) {
    uint32_t a;
    asm("{ .reg .u64 t; cvta.to.shared.u64 t, %1; cvt.u32.u64 %0, t; }" : "=r"(a) : "l"(p));
    return a;
}
static __device__ __forceinline__ void ldsm_x4(uint32_t* r, uint32_t addr) {
    asm volatile("ldmatrix.sync.aligned.m8n8.x4.shared.b16 {%0,%1,%2,%3}, [%4];"
                 : "=r"(r[0]), "=r"(r[1]), "=r"(r[2]), "=r"(r[3]) : "r"(addr));
}
static __device__ __forceinline__ void stsm_x4(uint32_t addr, uint32_t a, uint32_t b,
                                               uint32_t c, uint32_t d) {
    asm volatile("stmatrix.sync.aligned.m8n8.x4.shared.b16 [%0], {%1,%2,%3,%4};"
                 :: "r"(addr), "r"(a), "r"(b), "r"(c), "r"(d) : "memory");
}
static __device__ __forceinline__ void mma16816(float* c, const uint32_t* a,
                                                uint32_t b0, uint32_t b1) {
    asm volatile(
        "mma.sync.aligned.m16n8k16.row.col.f32.f16.f16.f32 "
        "{%0,%1,%2,%3}, {%4,%5,%6,%7}, {%8,%9}, {%0,%1,%2,%3};"
        : "+f"(c[0]), "+f"(c[1]), "+f"(c[2]), "+f"(c[3])
        : "r"(a[0]), "r"(a[1]), "r"(a[2]), "r"(a[3]), "r"(b0), "r"(b1));
}
static __device__ __forceinline__ uint32_t pack_h2(float a, float b) {
    __half2 h = __floats2half2_rn(a, b);
    return *(const uint32_t*)&h;
}
static __device__ __forceinline__ uint2 pack4(__half h0, __half h1, __half h2, __half h3) {
    __half2 a = __halves2half2(h0, h1);
    __half2 b = __halves2half2(h2, h3);
    uint2 r;
    r.x = *(const uint32_t*)&a;
    r.y = *(const uint32_t*)&b;
    return r;
}

// ---- init kernel: W1 fp16 fragments (replaying the ldsm path) + packed W2 ----
__global__ void gcn_init_kernel(const float* __restrict__ W1,
                                const float* __restrict__ W2)
{
    __shared__ __align__(16) char bsm[16384];    // BHI
    const int tid = threadIdx.x, wid = tid >> 5, lane = tid & 31;

    const float4* W1v = (const float4*)W1;
    #pragma unroll
    for (int t = 0; t < 8; t++) {
        int gi = tid + t * 256;          // gi = j*32 + f4
        int j = gi >> 5, f4 = gi & 31;
        float4 v = W1v[gi];
        __half h0 = __float2half_rn(v.x), h1 = __float2half_rn(v.y);
        __half h2 = __float2half_rn(v.z), h3 = __float2half_rn(v.w);
        uint32_t off = sw_off(j, f4 >> 1) + (uint32_t)(f4 & 1) * 8u;
        *(uint2*)(bsm + off) = pack4(h0, h1, h2, h3);
    }
    // gW2h[jp*32+m] = (W2[m][2jp], W2[m][2jp+1])
    for (int idx = tid; idx < 32 * 32; idx += 256) {
        int jp = idx >> 5, m = idx & 31;
        gW2h[idx] = __halves2half2(__float2half_rn(W2[m * H1 + 2 * jp]),
                                   __float2half_rn(W2[m * H1 + 2 * jp + 1]));
    }
    __syncthreads();

    const uint32_t sb = smem_u32(bsm);
    const int kc = wid;                  // warp w -> k-chunk w
    #pragma unroll
    for (int tp = 0; tp < 4; tp++) {
        int row = 16 * tp + ((lane >> 4) << 3) + (lane & 7);
        int chunk = kc * 2 + ((lane >> 3) & 1);
        uint32_t rh[4];
        ldsm_x4(rh, sb + sw_off(row, chunk));
        gBhi[(kc * 4 + tp) * 32 + lane] = make_uint4(rh[0], rh[1], rh[2], rh[3]);
    }
}

__global__ __launch_bounds__(THREADS, 4) void gcn_mma_kernel(
    const float* __restrict__ x,  const float* __restrict__ nb,
    const float* __restrict__ Wc, float* __restrict__ out, int n)
{
    extern __shared__ char sm[];
    const uint32_t sb = smem_u32(sm);
    const int tid = threadIdx.x, wid = tid >> 5, lane = tid & 31;
    const long gbase = (long)blockIdx.x * NPB;

    // ---- WCQ[mq*10+c] = float4 of Wc[c][mq*4 .. +3] ----
    if (tid < 80) {
        int mq = tid / 10, c = tid - mq * 10;
        const float* w = Wc + c * H2 + mq * 4;
        ((float4*)(sm + SM_WCQ))[tid] = make_float4(w[0], w[1], w[2], w[3]);
    }

    // ---- A rows: warp w owns rows w + 8t (t<15), 3 batches of 5 (MLP=5) ----
    #pragma unroll 1
    for (int b0 = 0; b0 < 15; b0 += 5) {
        float4 q[5];
        #pragma unroll
        for (int t = 0; t < 5; t++) {
            int r = wid + (b0 + t) * 8;
            q[t] = make_float4(0.f, 0.f, 0.f, 0.f);
            if (r < RV) {
                int node = r / 17, sub = r - node * 17;
                long gnode = gbase + node;
                if (gnode < n) {
                    const float4* src = (sub == 0)
                        ? (const float4*)(x + gnode * (long)F)
                        : (const float4*)(nb + (gnode * 16 + (sub - 1)) * (long)F);
                    q[t] = src[lane];
                }
            }
        }
        #pragma unroll
        for (int t = 0; t < 5; t++) {
            int r = wid + (b0 + t) * 8;
            if (r < RV) {
                float4 v = q[t];
                float ss = v.x * v.x + v.y * v.y + v.z * v.z + v.w * v.w;
                #pragma unroll
                for (int o = 16; o > 0; o >>= 1) ss += __shfl_xor_sync(0xffffffffu, ss, o);
                float inv = 1.f / fmaxf(sqrtf(ss), 1e-12f);
                __half h0 = __float2half_rn(v.x * inv);
                __half h1 = __float2half_rn(v.y * inv);
                __half h2 = __float2half_rn(v.z * inv);
                __half h3 = __float2half_rn(v.w * inv);
                uint32_t off = sw_off(r, lane >> 1) + (uint32_t)(lane & 1) * 8u;
                *(uint2*)(sm + SM_AHI + off) = pack4(h0, h1, h2, h3);
            }
        }
    }

    // ---- zero padding rows 119..127 ----
    if (tid < 144) {
        int r = RV + tid / 16, ch = tid & 15;
        *(uint4*)(sm + SM_AHI + sw_off(r, ch)) = make_uint4(0, 0, 0, 0);
    }
    __syncthreads();

    // ---- GEMM: warp grid 4(M) x 2(N); warp tile M=32 x N=32 ----
    const int wm = wid >> 1, wn = wid & 1;
    float acc[2][4][4];
    #pragma unroll
    for (int m = 0; m < 2; m++)
        #pragma unroll
        for (int ntl = 0; ntl < 4; ntl++)
            acc[m][ntl][0] = acc[m][ntl][1] = acc[m][ntl][2] = acc[m][ntl][3] = 0.f;

    {
        const int arow = 32 * wm + (lane & 15);
        const int asel = lane >> 4;
        const int tpb = 2 * wn;
        const uint4* pBhi = gBhi + tpb * 32 + lane;

        #pragma unroll
        for (int kc = 0; kc < 8; kc++) {
            uint4 bh0 = pBhi[kc * 128];
            uint4 bh1 = pBhi[kc * 128 + 32];

            uint32_t ahi[2][4];
            #pragma unroll
            for (int m = 0; m < 2; m++)
                ldsm_x4(ahi[m], sb + SM_AHI + sw_off(arow + 16 * m, kc * 2 + asel));

            #pragma unroll
            for (int m = 0; m < 2; m++) {
                mma16816(acc[m][0], ahi[m], bh0.x, bh0.y);
                mma16816(acc[m][1], ahi[m], bh0.z, bh0.w);
                mma16816(acc[m][2], ahi[m], bh1.x, bh1.y);
                mma16816(acc[m][3], ahi[m], bh1.z, bh1.w);
            }
        }
    }
    __syncthreads();   // A tile dead; fp16 Hbuf overlays it

    // ---- C frags -> fp16 Hbuf via stmatrix (coalesced, swizzle conflict-free) ----
    {
        const int g = lane >> 3;            // matrix index within x4
        const int mrow = lane & 7;
        #pragma unroll
        for (int m = 0; m < 2; m++) {
            int R = 32 * wm + 16 * m + (g & 1) * 8 + mrow;   // addr row for this lane
            #pragma unroll
            for (int h = 0; h < 2; h++) {    // ntl pairs {0,1}, {2,3}
                int ntl_g = h * 2 + (g >> 1);
                int chunk = 4 * wn + ntl_g;  // 16B col-chunk of this matrix
                uint32_t addr = sb + SM_HB + hb_off(R, chunk);
                stsm_x4(addr,
                        pack_h2(acc[m][h * 2 + 0][0], acc[m][h * 2 + 0][1]),
                        pack_h2(acc[m][h * 2 + 0][2], acc[m][h * 2 + 0][3]),
                        pack_h2(acc[m][h * 2 + 1][0], acc[m][h * 2 + 1][1]),
                        pack_h2(acc[m][h * 2 + 1][2], acc[m][h * 2 + 1][3]));
            }
        }
    }
    __syncthreads();

    // ---- per-node epilogue: warp = node (7 warps) ----
    long gnode = gbase + wid;
    if (wid < NPB && gnode < n) {
        int base = wid * 17;
        // stage 1: lane owns col-pair (2*lane, 2*lane+1); half2 reads, fp32 accum
        const int chv = lane >> 2;                 // chunk of this col-pair
        const uint32_t inch = (uint32_t)(lane & 3) * 4u;
        float2 hx = __half22float2(
            *(const __half2*)(sm + SM_HB + hb_off(base, chv) + inch));
        float r0 = 0.f, r1 = 0.f;
        #pragma unroll
        for (int k = 0; k < 16; k++) {
            int R = base + 1 + k;
            float2 h = __half22float2(
                *(const __half2*)(sm + SM_HB + hb_off(R, chv) + inch));
            r0 += fmaxf(hx.x + h.x, 0.f);
            r1 += fmaxf(hx.y + h.y, 0.f);
        }
        float* rb = (float*)(sm + SM_RBUF) + wid * 64;
        ((float2*)rb)[lane] = make_float2(r0, r1);
        __syncwarp();

        // stage 2: y[lane] = relu(sum_j r[j] * W2[lane][j]), vectorized
        const float4* rb4 = (const float4*)rb;
        const __half2* w2 = gW2h + lane;
        float y = 0.f;
        #pragma unroll
        for (int jq = 0; jq < 16; jq++) {
            float4 r4 = rb4[jq];
            __half2 wa = w2[(2 * jq) * 32];
            __half2 wb = w2[(2 * jq + 1) * 32];
            y += r4.x * __low2float(wa) + r4.y * __high2float(wa)
               + r4.z * __low2float(wb) + r4.w * __high2float(wb);
        }
        y = fmaxf(y, 0.f);
        float* yb = (float*)(sm + SM_YBUF) + wid * 32;
        yb[lane] = y;
        __syncwarp();

        // stage 3: out[c] = sum_m y[m] * Wc[c][m], float4 blocked
        if (lane < NC) {
            const float4* yb4 = (const float4*)yb;
            const float4* wcq = (const float4*)(sm + SM_WCQ);
            float o = 0.f;
            #pragma unroll
            for (int mq = 0; mq < 8; mq++) {
                float4 y4 = yb4[mq];
                float4 w4 = wcq[mq * 10 + lane];
                o += y4.x * w4.x + y4.y * w4.y + y4.z * w4.z + y4.w * w4.w;
            }
            out[gnode * NC + lane] = o;
        }
    }
}

extern "C" void kernel_launch(void* const* d_in, const int* in_sizes, int n_in,
                              void* d_out, int out_size)
{
    const float* x  = (const float*)d_in[0];
    const float* nb = (const float*)d_in[1];
    const float* W1 = (const float*)d_in[2];
    const float* W2 = (const float*)d_in[3];
    const float* Wc = (const float*)d_in[4];
    float* out = (float*)d_out;

    int n = in_sizes[0] / F;
    gcn_init_kernel<<<1, 256>>>(W1, W2);
    cudaFuncSetAttribute(gcn_mma_kernel,
                         cudaFuncAttributeMaxDynamicSharedMemorySize, SM_TOTAL);
    int grid = (n + NPB - 1) / NPB;
    gcn_mma_kernel<<<grid, THREADS, SM_TOTAL>>>(x, nb, Wc, out, n);
}

// round 13
// speedup vs baseline: 1.4415x; 1.0990x over previous
#include <cuda_runtime.h>
#include <cuda_fp16.h>
#include <stdint.h>

#define F    128
#define H1   64
#define H2   32
#define NC   10
#define NPB  7          // nodes per block
#define RV   119        // valid rows = 7*17
#define THREADS 256     // 8 warps: 4(M) x 2(N)

// ---- dynamic shared layout (padded, swizzle-free) ----
#define AROW_B  272          // A-tile row stride: 17 x 16B chunks (16 data + 1 pad)
#define HROW_B  144          // Hbuf row stride: 9 x 16B chunks (8 data + 1 pad)
#define SM_AHI  0            // 128 x 272B fp16 A tile (34816)
#define SM_HB   0            // 128 x 144B fp16 Hbuf (18432) overlays A after GEMM
#define SM_RBUF 34816        // 7*64*4 = 1792
#define SM_YBUF 36608        // 7*32*4 = 896
#define SM_WCQ  37504        // 80 float4 = 1280
#define SM_TOTAL 38784       // -> 4 CTAs/SM (smem & 64-reg cap)

// precomputed W1 MMA fragments + packed W2
__device__ uint4   gBhi[8 * 4 * 32];   // [kc][ntile tp][lane]
__device__ __half2 gW2h[32 * 32];      // [jp][m] = (W2[m][2jp], W2[m][2jp+1])

// init-kernel-only swizzled layout (row stride 256B, chunk ^= row&7)
static __device__ __forceinline__ uint32_t sw_off(int row, int chunk) {
    return (uint32_t)row * 256u + (uint32_t)((chunk ^ (row & 7)) << 4);
}
static __device__ __forceinline__ uint32_t smem_u32(const void* p) {
    uint32_t a;
    asm("{ .reg .u64 t; cvta.to.shared.u64 t, %1; cvt.u32.u64 %0, t; }" : "=r"(a) : "l"(p));
    return a;
}
static __device__ __forceinline__ void ldsm_x4(uint32_t* r, uint32_t addr) {
    asm volatile("ldmatrix.sync.aligned.m8n8.x4.shared.b16 {%0,%1,%2,%3}, [%4];"
                 : "=r"(r[0]), "=r"(r[1]), "=r"(r[2]), "=r"(r[3]) : "r"(addr));
}
static __device__ __forceinline__ void stsm_x4(uint32_t addr, uint32_t a, uint32_t b,
                                               uint32_t c, uint32_t d) {
    asm volatile("stmatrix.sync.aligned.m8n8.x4.shared.b16 [%0], {%1,%2,%3,%4};"
                 :: "r"(addr), "r"(a), "r"(b), "r"(c), "r"(d) : "memory");
}
static __device__ __forceinline__ void mma16816(float* c, const uint32_t* a,
                                                uint32_t b0, uint32_t b1) {
    asm volatile(
        "mma.sync.aligned.m16n8k16.row.col.f32.f16.f16.f32 "
        "{%0,%1,%2,%3}, {%4,%5,%6,%7}, {%8,%9}, {%0,%1,%2,%3};"
        : "+f"(c[0]), "+f"(c[1]), "+f"(c[2]), "+f"(c[3])
        : "r"(a[0]), "r"(a[1]), "r"(a[2]), "r"(a[3]), "r"(b0), "r"(b1));
}
static __device__ __forceinline__ uint32_t pack_h2(float a, float b) {
    __half2 h = __floats2half2_rn(a, b);
    return *(const uint32_t*)&h;
}
static __device__ __forceinline__ uint2 pack4(__half h0, __half h1, __half h2, __half h3) {
    __half2 a = __halves2half2(h0, h1);
    __half2 b = __halves2half2(h2, h3);
    uint2 r;
    r.x = *(const uint32_t*)&a;
    r.y = *(const uint32_t*)&b;
    return r;
}

// ---- init kernel: W1 fp16 fragments (replaying the ldsm path) + packed W2 ----
__global__ void gcn_init_kernel(const float* __restrict__ W1,
                                const float* __restrict__ W2)
{
    __shared__ __align__(16) char bsm[16384];    // BHI (swizzled, init-local)
    const int tid = threadIdx.x, wid = tid >> 5, lane = tid & 31;

    const float4* W1v = (const float4*)W1;
    #pragma unroll
    for (int t = 0; t < 8; t++) {
        int gi = tid + t * 256;          // gi = j*32 + f4
        int j = gi >> 5, f4 = gi & 31;
        float4 v = W1v[gi];
        __half h0 = __float2half_rn(v.x), h1 = __float2half_rn(v.y);
        __half h2 = __float2half_rn(v.z), h3 = __float2half_rn(v.w);
        uint32_t off = sw_off(j, f4 >> 1) + (uint32_t)(f4 & 1) * 8u;
        *(uint2*)(bsm + off) = pack4(h0, h1, h2, h3);
    }
    // gW2h[jp*32+m] = (W2[m][2jp], W2[m][2jp+1])
    for (int idx = tid; idx < 32 * 32; idx += 256) {
        int jp = idx >> 5, m = idx & 31;
        gW2h[idx] = __halves2half2(__float2half_rn(W2[m * H1 + 2 * jp]),
                                   __float2half_rn(W2[m * H1 + 2 * jp + 1]));
    }
    __syncthreads();

    const uint32_t sb = smem_u32(bsm);
    const int kc = wid;                  // warp w -> k-chunk w
    #pragma unroll
    for (int tp = 0; tp < 4; tp++) {
        int row = 16 * tp + ((lane >> 4) << 3) + (lane & 7);
        int chunk = kc * 2 + ((lane >> 3) & 1);
        uint32_t rh[4];
        ldsm_x4(rh, sb + sw_off(row, chunk));
        gBhi[(kc * 4 + tp) * 32 + lane] = make_uint4(rh[0], rh[1], rh[2], rh[3]);
    }
}

__global__ __launch_bounds__(THREADS, 4) void gcn_mma_kernel(
    const float* __restrict__ x,  const float* __restrict__ nb,
    const float* __restrict__ Wc, float* __restrict__ out, int n)
{
    extern __shared__ char sm[];
    const uint32_t sb = smem_u32(sm);
    const int tid = threadIdx.x, wid = tid >> 5, lane = tid & 31;
    const long gbase = (long)blockIdx.x * NPB;

    // ---- WCQ[mq*10+c] = float4 of Wc[c][mq*4 .. +3] ----
    if (tid < 80) {
        int mq = tid / 10, c = tid - mq * 10;
        const float* w = Wc + c * H2 + mq * 4;
        ((float4*)(sm + SM_WCQ))[tid] = make_float4(w[0], w[1], w[2], w[3]);
    }

    // ---- A rows: warp w owns rows w + 8t (t<15), 3 batches of 5 (MLP=5) ----
    #pragma unroll 1
    for (int b0 = 0; b0 < 15; b0 += 5) {
        float4 q[5];
        #pragma unroll
        for (int t = 0; t < 5; t++) {
            int r = wid + (b0 + t) * 8;
            q[t] = make_float4(0.f, 0.f, 0.f, 0.f);
            if (r < RV) {
                int node = r / 17, sub = r - node * 17;
                long gnode = gbase + node;
                if (gnode < n) {
                    const float4* src = (sub == 0)
                        ? (const float4*)(x + gnode * (long)F)
                        : (const float4*)(nb + (gnode * 16 + (sub - 1)) * (long)F);
                    q[t] = src[lane];
                }
            }
        }
        #pragma unroll
        for (int t = 0; t < 5; t++) {
            int r = wid + (b0 + t) * 8;
            if (r < RV) {
                float4 v = q[t];
                float ss = v.x * v.x + v.y * v.y + v.z * v.z + v.w * v.w;
                #pragma unroll
                for (int o = 16; o > 0; o >>= 1) ss += __shfl_xor_sync(0xffffffffu, ss, o);
                float inv = rsqrtf(fmaxf(ss, 1e-24f));
                __half h0 = __float2half_rn(v.x * inv);
                __half h1 = __float2half_rn(v.y * inv);
                __half h2 = __float2half_rn(v.z * inv);
                __half h3 = __float2half_rn(v.w * inv);
                uint32_t off = (uint32_t)r * AROW_B + (uint32_t)lane * 8u;
                *(uint2*)(sm + SM_AHI + off) = pack4(h0, h1, h2, h3);
            }
        }
    }

    // ---- zero padding rows 119..127 (9 rows x 16 data chunks) ----
    if (tid < 144) {
        int r = RV + tid / 16, ch = tid & 15;
        *(uint4*)(sm + SM_AHI + (uint32_t)r * AROW_B + (uint32_t)ch * 16u)
            = make_uint4(0, 0, 0, 0);
    }
    __syncthreads();

    // ---- GEMM: warp grid 4(M) x 2(N); warp tile M=32 x N=32 ----
    const int wm = wid >> 1, wn = wid & 1;
    float acc[2][4][4];
    #pragma unroll
    for (int m = 0; m < 2; m++)
        #pragma unroll
        for (int ntl = 0; ntl < 4; ntl++)
            acc[m][ntl][0] = acc[m][ntl][1] = acc[m][ntl][2] = acc[m][ntl][3] = 0.f;

    {
        const int arow = 32 * wm + (lane & 15);
        const int asel = lane >> 4;
        const int tpb = 2 * wn;
        const uint4* pBhi = gBhi + tpb * 32 + lane;
        const uint32_t abase0 = sb + SM_AHI + (uint32_t)arow * AROW_B
                              + (uint32_t)asel * 16u;

        #pragma unroll
        for (int kc = 0; kc < 8; kc++) {
            uint4 bh0 = pBhi[kc * 128];
            uint4 bh1 = pBhi[kc * 128 + 32];

            uint32_t ahi[2][4];
            #pragma unroll
            for (int m = 0; m < 2; m++)
                ldsm_x4(ahi[m], abase0 + (uint32_t)(16 * m) * AROW_B
                                      + (uint32_t)kc * 32u);

            #pragma unroll
            for (int m = 0; m < 2; m++) {
                mma16816(acc[m][0], ahi[m], bh0.x, bh0.y);
                mma16816(acc[m][1], ahi[m], bh0.z, bh0.w);
                mma16816(acc[m][2], ahi[m], bh1.x, bh1.y);
                mma16816(acc[m][3], ahi[m], bh1.z, bh1.w);
            }
        }
    }
    __syncthreads();   // A tile dead; fp16 Hbuf overlays it

    // ---- C frags -> fp16 Hbuf via stmatrix (coalesced, padded conflict-free) ----
    {
        const int g = lane >> 3;            // matrix index within x4
        const int mrow = lane & 7;
        #pragma unroll
        for (int m = 0; m < 2; m++) {
            int R = 32 * wm + 16 * m + (g & 1) * 8 + mrow;
            #pragma unroll
            for (int h = 0; h < 2; h++) {    // ntl pairs {0,1}, {2,3}
                int ntl_g = h * 2 + (g >> 1);
                int chunk = 4 * wn + ntl_g;
                uint32_t addr = sb + SM_HB + (uint32_t)R * HROW_B
                              + (uint32_t)chunk * 16u;
                stsm_x4(addr,
                        pack_h2(acc[m][h * 2 + 0][0], acc[m][h * 2 + 0][1]),
                        pack_h2(acc[m][h * 2 + 0][2], acc[m][h * 2 + 0][3]),
                        pack_h2(acc[m][h * 2 + 1][0], acc[m][h * 2 + 1][1]),
                        pack_h2(acc[m][h * 2 + 1][2], acc[m][h * 2 + 1][3]));
            }
        }
    }
    __syncthreads();

    // ---- per-node epilogue: warp = node (7 warps) ----
    long gnode = gbase + wid;
    if (wid < NPB && gnode < n) {
        // stage 1: lane owns col-pair (2*lane, 2*lane+1); linear pointer walk
        const char* hp = sm + SM_HB + (uint32_t)(wid * 17) * HROW_B
                       + (uint32_t)lane * 4u;
        float2 hx = __half22float2(*(const __half2*)hp);
        float r0 = 0.f, r1 = 0.f;
        #pragma unroll
        for (int k = 0; k < 16; k++) {
            hp += HROW_B;
            float2 h = __half22float2(*(const __half2*)hp);
            r0 += fmaxf(hx.x + h.x, 0.f);
            r1 += fmaxf(hx.y + h.y, 0.f);
        }
        float* rb = (float*)(sm + SM_RBUF) + wid * 64;
        ((float2*)rb)[lane] = make_float2(r0, r1);
        __syncwarp();

        // stage 2: y[lane] = relu(sum_j r[j] * W2[lane][j]), vectorized
        const float4* rb4 = (const float4*)rb;
        const __half2* w2 = gW2h + lane;
        float y = 0.f;
        #pragma unroll
        for (int jq = 0; jq < 16; jq++) {
            float4 r4 = rb4[jq];
            __half2 wa = w2[(2 * jq) * 32];
            __half2 wb = w2[(2 * jq + 1) * 32];
            y += r4.x * __low2float(wa) + r4.y * __high2float(wa)
               + r4.z * __low2float(wb) + r4.w * __high2float(wb);
        }
        y = fmaxf(y, 0.f);
        float* yb = (float*)(sm + SM_YBUF) + wid * 32;
        yb[lane] = y;
        __syncwarp();

        // stage 3: out[c] = sum_m y[m] * Wc[c][m], float4 blocked
        if (lane < NC) {
            const float4* yb4 = (const float4*)yb;
            const float4* wcq = (const float4*)(sm + SM_WCQ);
            float o = 0.f;
            #pragma unroll
            for (int mq = 0; mq < 8; mq++) {
                float4 y4 = yb4[mq];
                float4 w4 = wcq[mq * 10 + lane];
                o += y4.x * w4.x + y4.y * w4.y + y4.z * w4.z + y4.w * w4.w;
            }
            out[gnode * NC + lane] = o;
        }
    }
}

extern "C" void kernel_launch(void* const* d_in, const int* in_sizes, int n_in,
                              void* d_out, int out_size)
{
    const float* x  = (const float*)d_in[0];
    const float* nb = (const float*)d_in[1];
    const float* W1 = (const float*)d_in[2];
    const float* W2 = (const float*)d_in[3];
    const float* Wc = (const float*)d_in[4];
    float* out = (float*)d_out;

    int n = in_sizes[0] / F;
    gcn_init_kernel<<<1, 256>>>(W1, W2);
    cudaFuncSetAttribute(gcn_mma_kernel,
                         cudaFuncAttributeMaxDynamicSharedMemorySize, SM_TOTAL);
    int grid = (n + NPB - 1) / NPB;
    gcn_mma_kernel<<<grid, THREADS, SM_TOTAL>>>(x, nb, Wc, out, n);
}